// round 9
// baseline (speedup 1.0000x reference)
#include <cuda_runtime.h>
#include <cuda_bf16.h>
#include <math_constants.h>

// VectorQuantizer, D=1, N=512, x: [8,16,64,64] fp32.
// K1 (1 block): hybrid bitonic sort of 512 codes -> Eytzinger tree in gmem.
// K2 (256 blocks x 512 thr, PDL-overlapped with K1): 2 slices/block, 4
//     interleaved 9-level tree descents per thread (lo/hi neighbor tracking),
//     padded-smem transpose replicating the reference
//     view([B,H,W,C]).permute bug, fused loss; last block finalizes.

#define BQ 8
#define CQ 16
#define HQ 64
#define WQ 64
#define NCODE 512
#define NELEM (BQ*CQ*HQ*WQ)       // 524288
#define NBLK  256                 // main-kernel blocks (2 slices each)
#define NT    512

__device__ float g_eyt[NCODE];          // [0]=sorted[511], [1..511]=BFS pivots
__device__ float g_partial[NBLK];
__device__ unsigned int g_count = 0;

// ---------------- Kernel 1: sort + Eytzinger build ----------------
__global__ __launch_bounds__(NCODE) void vq_sort_kernel(const float* __restrict__ w) {
    __shared__ float sbuf[2][NCODE];
    const int tid = threadIdx.x;
    float sv = w[tid];
    int pb = 0;
    for (int k = 2; k <= NCODE; k <<= 1) {
        int j = k >> 1;
        for (; j >= 32; j >>= 1) {          // cross-warp via smem ping-pong
            sbuf[pb][tid] = sv;
            __syncthreads();
            float o = sbuf[pb][tid ^ j];
            bool keepMin = (((tid & j) == 0) == ((tid & k) == 0));
            sv = keepMin ? fminf(sv, o) : fmaxf(sv, o);
            pb ^= 1;
        }
#pragma unroll
        for (; j >= 1; j >>= 1) {           // intra-warp via shfl
            float o = __shfl_xor_sync(0xffffffffu, sv, j);
            bool keepMin = (((tid & j) == 0) == ((tid & k) == 0));
            sv = keepMin ? fminf(sv, o) : fmaxf(sv, o);
        }
    }
    // rank of sv == tid. Map sorted index -> Eytzinger node.
    // idx+1 = (2p+1)<<tz ; d = 8-tz ; node = (1<<d)+p ; idx=511 -> slot 0.
    int v = tid + 1;
    int tz = __ffs(v) - 1;
    int node;
    if (tz >= 9) node = 0;                  // sorted[511]
    else {
        int d = 8 - tz;
        int p = ((v >> tz) - 1) >> 1;
        node = (1 << d) + p;
    }
    g_eyt[node] = sv;
}

// ---------------- Kernel 2: quantize + permute + loss ----------------
__global__ __launch_bounds__(NT)
void vq_main_kernel(const float* __restrict__ x, float* __restrict__ out, int nq) {
    __shared__ float s_eyt[NCODE];
    __shared__ float s_tile[2][WQ * 17];    // padded transpose tiles, 2 slices
    __shared__ float s_warp[16];
    __shared__ int   s_last;

    const int tid = threadIdx.x;
    const int slice0 = blockIdx.x * 2;      // slice = b*64 + h

    // ---- j-order float2 gathers for both slices (independent of K1) ----
    float2 va = *(const float2*)(x + slice0 * 1024 + 2 * tid);
    float2 vb = *(const float2*)(x + (slice0 + 1) * 1024 + 2 * tid);

    // ---- wait for K1 (PDL); no-op when launched plainly ----
    cudaGridDependencySynchronize();

    const float maxcode = g_eyt[0];         // sorted[511]
    s_eyt[tid] = g_eyt[tid];
    __syncthreads();

    // ---- 4 interleaved 9-level descents with lo/hi neighbor tracking ----
    float v0 = va.x, v1 = va.y, v2 = vb.x, v3 = vb.y;
    float lo0 = -CUDART_INF_F, lo1 = lo0, lo2 = lo0, lo3 = lo0;
    float hi0 = maxcode, hi1 = maxcode, hi2 = maxcode, hi3 = maxcode;
    int k0 = 1, k1 = 1, k2 = 1, k3 = 1;
#pragma unroll
    for (int l = 0; l < 9; l++) {
        float p0 = s_eyt[k0], p1 = s_eyt[k1], p2 = s_eyt[k2], p3 = s_eyt[k3];
        bool r0 = (p0 <= v0), r1 = (p1 <= v1), r2 = (p2 <= v2), r3 = (p3 <= v3);
        lo0 = r0 ? p0 : lo0;  hi0 = r0 ? hi0 : p0;
        lo1 = r1 ? p1 : lo1;  hi1 = r1 ? hi1 : p1;
        lo2 = r2 ? p2 : lo2;  hi2 = r2 ? hi2 : p2;
        lo3 = r3 ? p3 : lo3;  hi3 = r3 ? hi3 : p3;
        k0 = 2 * k0 + (r0 ? 1 : 0);
        k1 = 2 * k1 + (r1 ? 1 : 0);
        k2 = 2 * k2 + (r2 ? 1 : 0);
        k3 = 2 * k3 + (r3 ? 1 : 0);
    }
    float q0 = ((v0 - lo0) <= (hi0 - v0)) ? lo0 : hi0;
    float q1 = ((v1 - lo1) <= (hi1 - v1)) ? lo1 : hi1;
    float q2 = ((v2 - lo2) <= (hi2 - v2)) ? lo2 : hi2;
    float q3 = ((v3 - lo3) <= (hi3 - v3)) ? lo3 : hi3;

    // ---- stage into transpose tiles: local j -> (w=j>>4, c=j&15) ----
    {
        int j0 = 2 * tid, j1 = 2 * tid + 1;
        s_tile[0][(j0 >> 4) * 17 + (j0 & 15)] = q0;
        s_tile[0][(j1 >> 4) * 17 + (j1 & 15)] = q1;
        s_tile[1][(j0 >> 4) * 17 + (j0 & 15)] = q2;
        s_tile[1][(j1 >> 4) * 17 + (j1 & 15)] = q3;
    }
    __syncthreads();

    // ---- transposed reads, float2 writes, fused loss ----
    const int t2 = 2 * tid;
    const int c2 = t2 >> 6, w2 = t2 & 63;   // w2 even: pair in same tile row
    float acc = 0.f;
#pragma unroll
    for (int s = 0; s < 2; s++) {
        int sl = slice0 + s;
        int b = sl >> 6, h = sl & 63;
        float qa = s_tile[s][w2 * 17 + c2];
        float qb = s_tile[s][(w2 + 1) * 17 + c2];
        int i = b * (CQ * HQ * WQ) + c2 * (HQ * WQ) + h * WQ + w2;
        float2 xv = *(const float2*)(x + i);
        float2 ov;
        ov.x = xv.x + (qa - xv.x);          // straight-through, literal
        ov.y = xv.y + (qb - xv.y);
        *(float2*)(out + i) = ov;
        float d0 = xv.x - qa, d1 = xv.y - qb;
        acc += d0 * d0 + d1 * d1;
    }

    // ---- block reduce (fixed order -> deterministic) ----
#pragma unroll
    for (int o = 16; o; o >>= 1) acc += __shfl_down_sync(0xffffffffu, acc, o);
    if ((tid & 31) == 0) s_warp[tid >> 5] = acc;
    __syncthreads();
    if (tid < 32) {
        float a = (tid < 16) ? s_warp[tid] : 0.f;
#pragma unroll
        for (int o = 8; o; o >>= 1) a += __shfl_down_sync(0xffffffffu, a, o);
        if (tid == 0) {
            g_partial[blockIdx.x] = a;
            __threadfence();
            unsigned int prev = atomicAdd(&g_count, 1u);
            s_last = (prev == (unsigned)(NBLK - 1)) ? 1 : 0;
        }
    }
    __syncthreads();

    // ---- last block finalizes losses (deterministic order) ----
    if (s_last) {
        __threadfence();
        float a = (tid < NBLK) ? g_partial[tid] : 0.f;
#pragma unroll
        for (int o = 16; o; o >>= 1) a += __shfl_down_sync(0xffffffffu, a, o);
        if ((tid & 31) == 0) s_warp[tid >> 5] = a;
        __syncthreads();
        if (tid == 0) {
            float total = 0.f;
#pragma unroll
            for (int i2 = 0; i2 < 8; i2++) total += s_warp[i2];
            float mean = total / (float)NELEM;
            out[nq]     = mean;             // q_latent_loss
            out[nq + 1] = mean;             // e_latent_loss
            g_count = 0;                    // reset for next graph replay
        }
    }
}

extern "C" void kernel_launch(void* const* d_in, const int* in_sizes, int n_in,
                              void* d_out, int out_size) {
    const float* x = (const float*)d_in[0];
    const float* w = (const float*)d_in[1];
    float* out = (float*)d_out;
    int nq = out_size - 2;

    vq_sort_kernel<<<1, NCODE>>>(w);

    // PDL launch: main kernel spins up while the sort runs; it synchronizes
    // via cudaGridDependencySynchronize() before reading g_eyt.
    cudaLaunchConfig_t cfg = {};
    cfg.gridDim = dim3(NBLK, 1, 1);
    cfg.blockDim = dim3(NT, 1, 1);
    cudaLaunchAttribute attr[1];
    attr[0].id = cudaLaunchAttributeProgrammaticStreamSerialization;
    attr[0].val.programmaticStreamSerializationAllowed = 1;
    cfg.attrs = attr;
    cfg.numAttrs = 1;
    if (cudaLaunchKernelEx(&cfg, vq_main_kernel, x, out, nq) != cudaSuccess) {
        vq_main_kernel<<<NBLK, NT>>>(x, out, nq);   // fallback: plain launch
    }
}

// round 14
// speedup vs baseline: 1.1889x; 1.1889x over previous
#include <cuda_runtime.h>
#include <cuda_bf16.h>
#include <math_constants.h>

// VectorQuantizer, D=1, N=512, x: [8,16,64,64] fp32 — single fused kernel, v6.
// 512 blocks x 512 threads (one (b,h) slice per block, 2 elems/thread).
// Block 0 hybrid-bitonic-sorts the 512 codes and publishes an Eytzinger tree
// (flag + fence); other blocks overlap their j-order x loads with the sort.
// 9-level descent with lo/hi tracking; padded-smem transpose of q replicates
// the reference view([B,H,W,C]).permute bug. The loss/straight-through MUST
// re-read x at the output index i (different element than the j-order input —
// this was the R12 bug). Fused loss; last block finalizes and resets state.

#define BQ 8
#define CQ 16
#define HQ 64
#define WQ 64
#define NCODE 512
#define NELEM (BQ*CQ*HQ*WQ)       // 524288
#define NBLK  (BQ*HQ)             // 512
#define NT    512

__device__ float g_eyt[NCODE];          // [0]=sorted[511], [1..511]=BFS pivots
__device__ float g_partial[NBLK];
__device__ unsigned int g_count = 0;
__device__ unsigned int g_flag = 0;

__global__ __launch_bounds__(NT, 4)
void vq_fused_kernel(const float* __restrict__ x, const float* __restrict__ w,
                     float* __restrict__ out, int nq) {
    __shared__ float s_eyt[NCODE];          // BFS pivot tree
    __shared__ float s_tq[WQ * 17];         // padded transpose tile (>=1024 fl)
    __shared__ float s_warp[16];
    __shared__ int   s_last;

    const int tid = threadIdx.x;
    const int slice = blockIdx.x;           // = b*64 + h

    // ---- j-order float2 gather (issued before any sort/spin) ----
    float2 vv = *(const float2*)(x + slice * 1024 + 2 * tid);

    if (blockIdx.x == 0) {
        // ---- hybrid bitonic sort; ping-pong in halves of s_tq ----
        float* sb0 = s_tq;
        float* sb1 = s_tq + NCODE;
        float sv = w[tid];
        int pb = 0;
        for (int k = 2; k <= NCODE; k <<= 1) {
            int j = k >> 1;
            for (; j >= 32; j >>= 1) {
                float* sb = pb ? sb1 : sb0;
                sb[tid] = sv;
                __syncthreads();
                float o = sb[tid ^ j];
                bool keepMin = (((tid & j) == 0) == ((tid & k) == 0));
                sv = keepMin ? fminf(sv, o) : fmaxf(sv, o);
                pb ^= 1;
            }
#pragma unroll
            for (; j >= 1; j >>= 1) {
                float o = __shfl_xor_sync(0xffffffffu, sv, j);
                bool keepMin = (((tid & j) == 0) == ((tid & k) == 0));
                sv = keepMin ? fminf(sv, o) : fmaxf(sv, o);
            }
        }
        // rank == tid. Eytzinger node: idx+1=(2p+1)<<tz, d=8-tz, node=(1<<d)+p.
        int v = tid + 1;
        int tz = __ffs(v) - 1;
        int node;
        if (tz >= 9) node = 0;              // sorted[511]
        else {
            int d = 8 - tz;
            int p = ((v >> tz) - 1) >> 1;
            node = (1 << d) + p;
        }
        g_eyt[node] = sv;
        s_eyt[node] = sv;                   // local copy, no gmem round-trip
        __threadfence();
        __syncthreads();                    // all gmem tree writes done
        if (tid == 0) atomicExch(&g_flag, 1u);
        __syncthreads();                    // s_tq free for reuse below
    } else {
        if (tid == 0) {
            while (atomicAdd(&g_flag, 0u) == 0u) __nanosleep(64);
        }
        __syncthreads();
        __threadfence();                    // order tree reads after flag
        s_eyt[tid] = g_eyt[tid];
        __syncthreads();
    }

    const float maxcode = s_eyt[0];         // sorted[511]

    // ---- two 9-level descents with lo/hi neighbor tracking ----
    float v0 = vv.x, v1 = vv.y;
    float lo0 = -CUDART_INF_F, lo1 = -CUDART_INF_F;
    float hi0 = maxcode, hi1 = maxcode;
    int k0 = 1, k1 = 1;
#pragma unroll
    for (int l = 0; l < 9; l++) {
        float p0 = s_eyt[k0], p1 = s_eyt[k1];
        bool r0 = (p0 <= v0), r1 = (p1 <= v1);
        lo0 = r0 ? p0 : lo0;  hi0 = r0 ? hi0 : p0;
        lo1 = r1 ? p1 : lo1;  hi1 = r1 ? hi1 : p1;
        k0 = 2 * k0 + (r0 ? 1 : 0);
        k1 = 2 * k1 + (r1 ? 1 : 0);
    }
    float q0 = ((v0 - lo0) <= (hi0 - v0)) ? lo0 : hi0;
    float q1 = ((v1 - lo1) <= (hi1 - v1)) ? lo1 : hi1;

    // ---- stage q into transpose tile: local j -> (w=j>>4, c=j&15) ----
    {
        int j0 = 2 * tid, j1 = 2 * tid + 1;
        s_tq[(j0 >> 4) * 17 + (j0 & 15)] = q0;
        s_tq[(j1 >> 4) * 17 + (j1 & 15)] = q1;
    }
    __syncthreads();

    // ---- transposed q reads, i-order x reload, float2 write, fused loss ----
    const int b = slice >> 6, h = slice & 63;
    const int t2 = 2 * tid;
    const int c2 = t2 >> 6, w2 = t2 & 63;   // w2 even: adjacent tile rows
    float qa = s_tq[w2 * 17 + c2];
    float qb = s_tq[(w2 + 1) * 17 + c2];
    int i = b * (CQ * HQ * WQ) + c2 * (HQ * WQ) + h * WQ + w2;
    float2 xv = *(const float2*)(x + i);    // REQUIRED: x at output index
    float2 ov;
    ov.x = xv.x + (qa - xv.x);              // straight-through, literal
    ov.y = xv.y + (qb - xv.y);
    *(float2*)(out + i) = ov;
    float d0 = xv.x - qa, d1 = xv.y - qb;
    float acc = d0 * d0 + d1 * d1;

    // ---- block reduce (fixed order -> deterministic) ----
#pragma unroll
    for (int o = 16; o; o >>= 1) acc += __shfl_down_sync(0xffffffffu, acc, o);
    if ((tid & 31) == 0) s_warp[tid >> 5] = acc;
    __syncthreads();
    if (tid < 32) {
        float a = (tid < 16) ? s_warp[tid] : 0.f;
#pragma unroll
        for (int o = 8; o; o >>= 1) a += __shfl_down_sync(0xffffffffu, a, o);
        if (tid == 0) {
            g_partial[blockIdx.x] = a;
            __threadfence();
            unsigned int prev = atomicAdd(&g_count, 1u);
            s_last = (prev == (unsigned)(NBLK - 1)) ? 1 : 0;
        }
    }
    __syncthreads();

    // ---- last block finalizes losses, resets state for graph replay ----
    if (s_last) {
        __threadfence();
        float a = g_partial[tid];
#pragma unroll
        for (int o = 16; o; o >>= 1) a += __shfl_down_sync(0xffffffffu, a, o);
        if ((tid & 31) == 0) s_warp[tid >> 5] = a;
        __syncthreads();
        if (tid == 0) {
            float total = 0.f;
#pragma unroll
            for (int i2 = 0; i2 < 16; i2++) total += s_warp[i2];
            float mean = total / (float)NELEM;
            out[nq]     = mean;             // q_latent_loss
            out[nq + 1] = mean;             // e_latent_loss
            g_count = 0;
            atomicExch(&g_flag, 0u);        // reset for next graph replay
        }
    }
}

extern "C" void kernel_launch(void* const* d_in, const int* in_sizes, int n_in,
                              void* d_out, int out_size) {
    const float* x = (const float*)d_in[0];
    const float* w = (const float*)d_in[1];
    float* out = (float*)d_out;
    int nq = out_size - 2;
    vq_fused_kernel<<<NBLK, NT>>>(x, w, out, nq);
}

// round 16
// speedup vs baseline: 1.3145x; 1.1057x over previous
#include <cuda_runtime.h>
#include <cuda_bf16.h>
#include <math_constants.h>

// VectorQuantizer, D=1, N=512, x: [8,16,64,64] fp32 — single fused kernel, v7.
// 512 blocks x 512 threads (one (b,h) slice per block, 2 elems/thread).
// Block 0 hybrid-bitonic-sorts the 512 codes and publishes an Eytzinger tree
// (volatile flag + fences; NO atomic polling — that was R14's stall storm).
// Both x loads (j-order input, i-order for loss) are issued at the very top so
// their latency hides behind the sort-wait/descent. 9-level descent with lo/hi
// tracking; padded-smem transpose replicates the reference
// view([B,H,W,C]).permute bug. Fused loss; last block finalizes and resets.

#define BQ 8
#define CQ 16
#define HQ 64
#define WQ 64
#define NCODE 512
#define NELEM (BQ*CQ*HQ*WQ)       // 524288
#define NBLK  (BQ*HQ)             // 512
#define NT    512

__device__ float g_eyt[NCODE];          // [0]=sorted[511], [1..511]=BFS pivots
__device__ float g_partial[NBLK];
__device__ unsigned int g_count = 0;
__device__ volatile unsigned int g_flag = 0;

__global__ __launch_bounds__(NT, 4)
void vq_fused_kernel(const float* __restrict__ x, const float* __restrict__ w,
                     float* __restrict__ out, int nq) {
    __shared__ float s_eyt[NCODE];          // BFS pivot tree
    __shared__ float s_tq[WQ * 17];         // padded transpose tile (1088 >= 1024)
    __shared__ float s_warp[16];
    __shared__ int   s_last;

    const int tid = threadIdx.x;
    const int slice = blockIdx.x;           // = b*64 + h
    const int b = slice >> 6, h = slice & 63;
    const int t2 = 2 * tid;
    const int c2 = t2 >> 6, w2 = t2 & 63;   // output-tile coords (w2 even)
    const int i = b * (CQ * HQ * WQ) + c2 * (HQ * WQ) + h * WQ + w2;

    // ---- issue BOTH gmem loads up front; latency hides behind sort/descent ----
    float2 vv = *(const float2*)(x + slice * 1024 + t2);   // j-order input
    float2 xv = *(const float2*)(x + i);                   // i-order, for loss/ST

    if (blockIdx.x == 0) {
        // ---- hybrid bitonic sort; ping-pong in halves of s_tq ----
        float* sb0 = s_tq;
        float* sb1 = s_tq + NCODE;
        float sv = w[tid];
        int pb = 0;
        for (int k = 2; k <= NCODE; k <<= 1) {
            int j = k >> 1;
            for (; j >= 32; j >>= 1) {
                float* sb = pb ? sb1 : sb0;
                sb[tid] = sv;
                __syncthreads();
                float o = sb[tid ^ j];
                bool keepMin = (((tid & j) == 0) == ((tid & k) == 0));
                sv = keepMin ? fminf(sv, o) : fmaxf(sv, o);
                pb ^= 1;
            }
#pragma unroll
            for (; j >= 1; j >>= 1) {
                float o = __shfl_xor_sync(0xffffffffu, sv, j);
                bool keepMin = (((tid & j) == 0) == ((tid & k) == 0));
                sv = keepMin ? fminf(sv, o) : fmaxf(sv, o);
            }
        }
        // rank == tid. Eytzinger node: idx+1=(2p+1)<<tz, d=8-tz, node=(1<<d)+p.
        int v = tid + 1;
        int tz = __ffs(v) - 1;
        int node;
        if (tz >= 9) node = 0;              // sorted[511]
        else {
            int d = 8 - tz;
            int p = ((v >> tz) - 1) >> 1;
            node = (1 << d) + p;
        }
        g_eyt[node] = sv;
        s_eyt[node] = sv;                   // local copy, no gmem round-trip
        __syncthreads();                    // all g_eyt writes issued
        __threadfence();                    // release: writes visible chip-wide
        if (tid == 0) g_flag = 1u;          // volatile store
        __syncthreads();                    // s_tq free for reuse below
    } else {
        if (tid == 0) {
            while (g_flag == 0u) __nanosleep(128);   // volatile load poll
        }
        __syncthreads();
        __threadfence();                    // acquire: order tree reads after flag
        s_eyt[tid] = g_eyt[tid];
        __syncthreads();
    }

    const float maxcode = s_eyt[0];         // sorted[511]

    // ---- two 9-level descents with lo/hi neighbor tracking ----
    float v0 = vv.x, v1 = vv.y;
    float lo0 = -CUDART_INF_F, lo1 = -CUDART_INF_F;
    float hi0 = maxcode, hi1 = maxcode;
    int k0 = 1, k1 = 1;
#pragma unroll
    for (int l = 0; l < 9; l++) {
        float p0 = s_eyt[k0], p1 = s_eyt[k1];
        bool r0 = (p0 <= v0), r1 = (p1 <= v1);
        lo0 = r0 ? p0 : lo0;  hi0 = r0 ? hi0 : p0;
        lo1 = r1 ? p1 : lo1;  hi1 = r1 ? hi1 : p1;
        k0 = 2 * k0 + (r0 ? 1 : 0);
        k1 = 2 * k1 + (r1 ? 1 : 0);
    }
    float q0 = ((v0 - lo0) <= (hi0 - v0)) ? lo0 : hi0;
    float q1 = ((v1 - lo1) <= (hi1 - v1)) ? lo1 : hi1;

    // ---- stage q into transpose tile: local j -> (w=j>>4, c=j&15) ----
    {
        int j0 = t2, j1 = t2 + 1;
        s_tq[(j0 >> 4) * 17 + (j0 & 15)] = q0;
        s_tq[(j1 >> 4) * 17 + (j1 & 15)] = q1;
    }
    __syncthreads();

    // ---- transposed q reads, float2 write, fused loss (xv already in flight) ----
    float qa = s_tq[w2 * 17 + c2];
    float qb = s_tq[(w2 + 1) * 17 + c2];
    float2 ov;
    ov.x = xv.x + (qa - xv.x);              // straight-through, literal
    ov.y = xv.y + (qb - xv.y);
    *(float2*)(out + i) = ov;
    float d0 = xv.x - qa, d1 = xv.y - qb;
    float acc = d0 * d0 + d1 * d1;

    // ---- block reduce (fixed order -> deterministic) ----
#pragma unroll
    for (int o = 16; o; o >>= 1) acc += __shfl_down_sync(0xffffffffu, acc, o);
    if ((tid & 31) == 0) s_warp[tid >> 5] = acc;
    __syncthreads();
    if (tid < 32) {
        float a = (tid < 16) ? s_warp[tid] : 0.f;
#pragma unroll
        for (int o = 8; o; o >>= 1) a += __shfl_down_sync(0xffffffffu, a, o);
        if (tid == 0) {
            g_partial[blockIdx.x] = a;
            __threadfence();
            unsigned int prev = atomicAdd(&g_count, 1u);
            s_last = (prev == (unsigned)(NBLK - 1)) ? 1 : 0;
        }
    }
    __syncthreads();

    // ---- last block finalizes losses, resets state for graph replay ----
    if (s_last) {
        __threadfence();
        float a = g_partial[tid];
#pragma unroll
        for (int o = 16; o; o >>= 1) a += __shfl_down_sync(0xffffffffu, a, o);
        if ((tid & 31) == 0) s_warp[tid >> 5] = a;
        __syncthreads();
        if (tid == 0) {
            float total = 0.f;
#pragma unroll
            for (int i2 = 0; i2 < 16; i2++) total += s_warp[i2];
            float mean = total / (float)NELEM;
            out[nq]     = mean;             // q_latent_loss
            out[nq + 1] = mean;             // e_latent_loss
            g_count = 0;
            g_flag = 0u;                    // reset for next graph replay
            __threadfence();
        }
    }
}

extern "C" void kernel_launch(void* const* d_in, const int* in_sizes, int n_in,
                              void* d_out, int out_size) {
    const float* x = (const float*)d_in[0];
    const float* w = (const float*)d_in[1];
    float* out = (float*)d_out;
    int nq = out_size - 2;
    vq_fused_kernel<<<NBLK, NT>>>(x, w, out, nq);
}